// round 2
// baseline (speedup 1.0000x reference)
#include <cuda_runtime.h>
#include <stdint.h>

#define B_IMG 8
#define N_PROP 2000
#define NCLS 91
#define NFG 90
#define NCAND (N_PROP*NFG)
#define K_TOP 2048
#define DETS 100
#define IMG_WF 1333.0f
#define IMG_HF 800.0f
#define SCORE_T 0.05f
#define NMS_T 0.5f
#define MIN_SZ 0.01f
#define XCLIP 4.135166556742356f
#define FILL_HI 0xBF800000u   /* == desc_key(-1.0f) */

__device__ unsigned long long g_keys[(size_t)B_IMG * NCAND];
__device__ int g_count[B_IMG];
__device__ float2 g_smax[B_IMG * N_PROP];
__device__ int g_cand_idx[B_IMG * K_TOP];
__device__ unsigned char g_cand_valid[B_IMG * K_TOP];
__device__ float4 g_cand_box[B_IMG * K_TOP];
__device__ float g_cand_score[B_IMG * K_TOP];
__device__ int g_cand_label[B_IMG * K_TOP];
__device__ unsigned int g_maxc[B_IMG];

// accurate expf, immune to --use_fast_math (~2 ulp)
__device__ __forceinline__ float exp_acc(float x){
    float j = fmaf(x, 1.442695041f, 12582912.0f) - 12582912.0f;
    float f = fmaf(j, -0.693145752f, x);
    f = fmaf(j, -1.42860677e-6f, f);
    float r =          1.37805939e-3f;
    r = fmaf(r, f, 8.37312452e-3f);
    r = fmaf(r, f, 4.16695364e-2f);
    r = fmaf(r, f, 1.66664720e-1f);
    r = fmaf(r, f, 4.99999851e-1f);
    r = fmaf(r, f, 1.0f);
    r = fmaf(r, f, 1.0f);
    return ldexpf(r, (int)j);
}

// higher score -> smaller key
__device__ __forceinline__ unsigned int desc_key(float f){
    unsigned int u = __float_as_uint(f);
    u = (u & 0x80000000u) ? ~u : (u | 0x80000000u);
    return ~u;
}

__device__ __forceinline__ bool decode_box(float4 p, float4 r, float4& bx){
    float w  = p.z - p.x, h  = p.w - p.y;
    float cx = p.x + 0.5f*w, cy = p.y + 0.5f*h;
    float dx = __fdiv_rn(r.x, 10.0f), dy = __fdiv_rn(r.y, 10.0f);
    float dw = fminf(__fdiv_rn(r.z, 5.0f), XCLIP);
    float dh = fminf(__fdiv_rn(r.w, 5.0f), XCLIP);
    float pcx = dx*w + cx, pcy = dy*h + cy;
    float pw = exp_acc(dw)*w, ph = exp_acc(dh)*h;
    bx.x = fminf(fmaxf(pcx - 0.5f*pw, 0.0f), IMG_WF);
    bx.y = fminf(fmaxf(pcy - 0.5f*ph, 0.0f), IMG_HF);
    bx.z = fminf(fmaxf(pcx + 0.5f*pw, 0.0f), IMG_WF);
    bx.w = fminf(fmaxf(pcy + 0.5f*ph, 0.0f), IMG_HF);
    return ((bx.z - bx.x) >= MIN_SZ) && ((bx.w - bx.y) >= MIN_SZ);
}

__device__ __forceinline__ bool cand_full(int img, int idx,
        const float* __restrict__ logits, const float4* __restrict__ regs4,
        const float4* __restrict__ props4, float& score, float4& bx){
    int i_local = idx / NFG;
    int c = idx - i_local*NFG + 1;
    int i = img*N_PROP + i_local;
    float2 md = g_smax[i];
    float l = logits[(size_t)i*NCLS + c];
    score = __fdiv_rn(exp_acc(l - md.x), md.y);
    bool szok = decode_box(props4[i], regs4[(size_t)i*NCLS + c], bx);
    return (score > SCORE_T) && szok;
}

__global__ void k_init(){
    int t = threadIdx.x;
    if (t < B_IMG){ g_count[t] = 0; g_maxc[t] = 0u; }
}

__global__ void __launch_bounds__(256) k_score(const float* __restrict__ logits,
                        const float4* __restrict__ regs4,
                        const float4* __restrict__ props4){
    __shared__ int s_cnt, s_base;
    int warp = threadIdx.x >> 5, lane = threadIdx.x & 31;
    int p = blockIdx.x*8 + warp;
    int img = p / N_PROP;
    int i_local = p - img*N_PROP;
    if (threadIdx.x == 0) s_cnt = 0;
    __syncthreads();
    const float* lrow = logits + (size_t)p*NCLS;
    float l0 = lrow[lane];
    float l1 = lrow[lane+32];
    float l2 = (lane < NCLS-64) ? lrow[lane+64] : -3.0e38f;
    float m = fmaxf(fmaxf(l0,l1), l2);
    #pragma unroll
    for (int o=16;o;o>>=1) m = fmaxf(m, __shfl_xor_sync(0xFFFFFFFFu, m, o));
    float e0 = exp_acc(l0-m), e1 = exp_acc(l1-m);
    float e2 = (lane < NCLS-64) ? exp_acc(l2-m) : 0.0f;
    float s = e0+e1+e2;
    #pragma unroll
    for (int o=16;o;o>>=1) s += __shfl_xor_sync(0xFFFFFFFFu, s, o);
    if (lane == 0) g_smax[p] = make_float2(m, s);
    float4 pr = props4[p];
    unsigned long long karr[3]; int cnt = 0;
    #pragma unroll
    for (int slot=0; slot<3; slot++){
        int c = lane + slot*32;
        float e = (slot==0) ? e0 : ((slot==1) ? e1 : e2);
        if (c >= 1 && c < NCLS){
            float score = __fdiv_rn(e, s);
            if (score > SCORE_T){
                float4 bx;
                if (decode_box(pr, regs4[(size_t)p*NCLS + c], bx)){
                    unsigned int hi = desc_key(score);
                    karr[cnt++] = (((unsigned long long)hi) << 32)
                                | (unsigned int)(i_local*NFG + (c-1));
                }
            }
        }
    }
    int pos = cnt ? atomicAdd(&s_cnt, cnt) : 0;
    __syncthreads();
    if (threadIdx.x == 0) s_base = atomicAdd(&g_count[img], s_cnt);
    __syncthreads();
    for (int k2=0; k2<cnt; k2++)
        g_keys[(size_t)img*NCAND + s_base + pos + k2] = karr[k2];
}

__global__ void __launch_bounds__(512) k_select(const float* __restrict__ logits,
                         const float4* __restrict__ regs4,
                         const float4* __restrict__ props4){
    int img = blockIdx.x, tid = threadIdx.x;
    __shared__ unsigned long long skeys[K_TOP];
    __shared__ unsigned int hist[256];
    __shared__ int wsum[16];
    __shared__ int s_digit, s_below, s_app, s_comp;
    unsigned long long* buf = g_keys + (size_t)img*NCAND;
    int n0 = g_count[img];
    int n = n0;

    if (n0 < K_TOP){
        if (tid == 0) s_app = 0;
        __syncthreads();
        int wid = tid>>5, ln = tid&31;
        for (int base=0; base < NCAND; base += 512){
            if (s_app >= K_TOP - n0) break;
            int idx = base + tid;
            bool flag = false;
            if (idx < NCAND){
                float sc; float4 bx;
                flag = !cand_full(img, idx, logits, regs4, props4, sc, bx);
            }
            unsigned int bal = __ballot_sync(0xFFFFFFFFu, flag);
            if (ln == 0) wsum[wid] = __popc(bal);
            __syncthreads();
            int off=0, total=0;
            #pragma unroll
            for (int wk=0; wk<16; wk++){ int v=wsum[wk]; if (wk<wid) off+=v; total+=v; }
            int rank = off + __popc(bal & ((1u<<ln)-1u));
            int need = K_TOP - n0 - s_app;
            if (flag && rank < need)
                buf[n0 + s_app + rank] =
                    (((unsigned long long)FILL_HI)<<32) | (unsigned int)idx;
            __syncthreads();
            if (tid == 0) s_app += (total < need ? total : need);
            __syncthreads();
        }
        n = K_TOP;
        __syncthreads();
    }

    unsigned long long T = ~0ull;
    if (n > K_TOP){
        unsigned long long prefix = 0, himask = 0;
        unsigned int kk = K_TOP;
        for (int pass=0; pass<8; pass++){
            int shift = 56 - 8*pass;
            for (int d=tid; d<256; d+=512) hist[d] = 0u;
            __syncthreads();
            for (int jj=tid; jj<n; jj+=512){
                unsigned long long key = buf[jj];
                if ((key & himask) == prefix)
                    atomicAdd(&hist[(unsigned int)(key>>shift)&255u], 1u);
            }
            __syncthreads();
            if (tid == 0){
                unsigned int cum = 0;
                for (int d=0; d<256; d++){
                    unsigned int c = hist[d];
                    if (cum + c >= kk){ s_digit=d; s_below=(int)cum; break; }
                    cum += c;
                }
            }
            __syncthreads();
            prefix |= ((unsigned long long)(unsigned int)s_digit) << shift;
            kk -= (unsigned int)s_below;
            himask = (~0ull) << shift;
            __syncthreads();
        }
        T = prefix;
    }

    if (tid == 0) s_comp = 0;
    __syncthreads();
    for (int jj=tid; jj<n; jj+=512){
        unsigned long long key = buf[jj];
        if (key <= T){
            int pp = atomicAdd(&s_comp, 1);
            if (pp < K_TOP) skeys[pp] = key;
        }
    }
    __syncthreads();

    for (unsigned int k=2; k<=K_TOP; k<<=1){
        for (unsigned int j=k>>1; j>0; j>>=1){
            for (int ii=tid; ii<K_TOP; ii+=512){
                int ixj = ii ^ (int)j;
                if (ixj > ii){
                    unsigned long long a = skeys[ii], b2 = skeys[ixj];
                    bool up = ((ii & (int)k) == 0);
                    if ((a > b2) == up){ skeys[ii]=b2; skeys[ixj]=a; }
                }
            }
            __syncthreads();
        }
    }

    for (int s2=tid; s2<K_TOP; s2+=512){
        unsigned long long key = skeys[s2];
        g_cand_idx[img*K_TOP + s2] = (int)(key & 0xFFFFFFFFull);
        g_cand_valid[img*K_TOP + s2] = ((unsigned int)(key>>32) != FILL_HI) ? 1 : 0;
    }
}

__global__ void __launch_bounds__(256) k_decode(const float* __restrict__ logits,
                         const float4* __restrict__ regs4,
                         const float4* __restrict__ props4){
    int t = blockIdx.x*blockDim.x + threadIdx.x;
    if (t >= B_IMG*K_TOP) return;
    int img = t >> 11;
    int idx = g_cand_idx[t];
    float sc; float4 bx;
    cand_full(img, idx, logits, regs4, props4, sc, bx);
    g_cand_box[t] = bx;
    g_cand_score[t] = sc;
    int i_local = idx / NFG;
    g_cand_label[t] = idx - i_local*NFG + 1;
    float mx = fmaxf(fmaxf(bx.x, bx.y), fmaxf(bx.z, bx.w));
    #pragma unroll
    for (int o=16;o;o>>=1) mx = fmaxf(mx, __shfl_xor_sync(0xFFFFFFFFu, mx, o));
    if ((threadIdx.x & 31) == 0) atomicMax(&g_maxc[img], __float_as_uint(mx));
}

__global__ void __launch_bounds__(1024) k_nms(float* __restrict__ out){
    int img = blockIdx.x, tid = threadIdx.x;
    __shared__ float4 s_ob[K_TOP];
    __shared__ float s_area[K_TOP];
    __shared__ unsigned char s_lab[K_TOP];
    __shared__ unsigned short s_ord[K_TOP];
    __shared__ int s_start[92];
    __shared__ int s_hist[92];
    __shared__ unsigned int s_keep[64];
    __shared__ int s_wbase[64];
    __shared__ int s_tot;

    float mul = __uint_as_float(g_maxc[img]) + 1.0f;
    if (tid < 92) s_hist[tid] = 0;
    if (tid < 64) s_keep[tid] = 0u;
    __syncthreads();
    for (int t = tid; t < K_TOP; t += 1024){
        float4 b = g_cand_box[img*K_TOP + t];
        int lab = g_cand_label[img*K_TOP + t];
        float off = (float)lab * mul;
        float4 ob = make_float4(b.x+off, b.y+off, b.z+off, b.w+off);
        s_ob[t] = ob;
        s_area[t] = (ob.z-ob.x)*(ob.w-ob.y);
        s_lab[t] = (unsigned char)lab;
        atomicAdd(&s_hist[lab], 1);
        if (g_cand_valid[img*K_TOP + t]) atomicOr(&s_keep[t>>5], 1u<<(t&31));
    }
    __syncthreads();
    if (tid == 0){ int acc=0; for (int l=0;l<92;l++){ s_start[l]=acc; acc+=s_hist[l]; } }
    __syncthreads();
    int warp = tid>>5, lane = tid&31;
    for (int k=0;k<3;k++){
        int lab = 1 + warp + k*32;
        if (lab <= NFG){
            int cur = 0, st = s_start[lab];
            for (int base=0; base<K_TOP; base+=32){
                int t = base + lane;
                bool mm = (s_lab[t] == (unsigned char)lab);
                unsigned int bal = __ballot_sync(0xFFFFFFFFu, mm);
                if (mm) s_ord[st + cur + __popc(bal & ((1u<<lane)-1u))]
                            = (unsigned short)t;
                cur += __popc(bal);
            }
        }
    }
    __syncthreads();
    for (int k=0;k<3;k++){
        int lab = 1 + warp + k*32;
        if (lab > NFG) continue;
        int st = s_start[lab], g = s_hist[lab];
        for (int i=0; i<g; i++){
            int ci = s_ord[st+i];
            unsigned int kw = s_keep[ci>>5];
            if (!((kw >> (ci&31)) & 1u)){ __syncwarp(); continue; }
            float4 a = s_ob[ci]; float aa = s_area[ci];
            for (int j = i+1+lane; j < g; j += 32){
                int cj = s_ord[st+j];
                float4 bb = s_ob[cj];
                float ltx = fmaxf(a.x, bb.x), lty = fmaxf(a.y, bb.y);
                float rbx = fminf(a.z, bb.z), rby = fminf(a.w, bb.w);
                float wx = fmaxf(rbx-ltx, 0.0f), wy = fmaxf(rby-lty, 0.0f);
                float inter = wx*wy;
                float iou = __fdiv_rn(inter, aa + s_area[cj] - inter);
                if (iou > NMS_T) atomicAnd(&s_keep[cj>>5], ~(1u<<(cj&31)));
            }
            __syncwarp();
        }
    }
    __syncthreads();
    if (warp == 0){
        unsigned int w0 = s_keep[lane];
        int c0 = __popc(w0), sc0 = c0;
        #pragma unroll
        for (int o=1;o<32;o<<=1){ int v=__shfl_up_sync(0xFFFFFFFFu,sc0,o); if(lane>=o) sc0+=v; }
        s_wbase[lane] = sc0 - c0;
        int tot0 = __shfl_sync(0xFFFFFFFFu, sc0, 31);
        unsigned int w1 = s_keep[32+lane];
        int c1 = __popc(w1), sc1 = c1;
        #pragma unroll
        for (int o=1;o<32;o<<=1){ int v=__shfl_up_sync(0xFFFFFFFFu,sc1,o); if(lane>=o) sc1+=v; }
        s_wbase[32+lane] = tot0 + sc1 - c1;
        if (lane == 31) s_tot = tot0 + sc1;
    }
    __syncthreads();
    int K = s_tot;
    for (int t = tid; t < K_TOP; t += 1024){
        unsigned int w = s_keep[t>>5];
        int kbefore = s_wbase[t>>5] + __popc(w & ((1u<<(t&31))-1u));
        bool kept = (w >> (t&31)) & 1u;
        int slot = -1; float oscore = 0.0f;
        if (kept){
            if (kbefore < DETS){ slot = kbefore; oscore = g_cand_score[img*K_TOP+t]; }
        } else if (K < DETS){
            int s2 = K + (t - kbefore);
            if (s2 < DETS){ slot = s2; oscore = -1.0f; }
        }
        if (slot >= 0){
            ((float4*)out)[img*DETS + slot] = g_cand_box[img*K_TOP + t];
            out[B_IMG*DETS*4 + img*DETS + slot] = oscore;
            out[B_IMG*DETS*5 + img*DETS + slot] = (float)g_cand_label[img*K_TOP + t];
        }
    }
}

extern "C" void kernel_launch(void* const* d_in, const int* in_sizes, int n_in,
                              void* d_out, int out_size) {
    const float*  logits = (const float*)d_in[0];
    const float4* regs4  = (const float4*)d_in[1];
    const float4* props4 = (const float4*)d_in[2];
    float* out = (float*)d_out;
    k_init<<<1, 32>>>();
    k_score<<<(B_IMG*N_PROP)/8, 256>>>(logits, regs4, props4);
    k_select<<<B_IMG, 512>>>(logits, regs4, props4);
    k_decode<<<(B_IMG*K_TOP + 255)/256, 256>>>(logits, regs4, props4);
    k_nms<<<B_IMG, 1024>>>(out);
}

// round 3
// speedup vs baseline: 1.3376x; 1.3376x over previous
#include <cuda_runtime.h>
#include <stdint.h>

typedef unsigned long long u64;
typedef unsigned int u32;

#define B_IMG 8
#define N_PROP 2000
#define NCLS 91
#define NFG 90
#define NCAND (N_PROP*NFG)
#define K_TOP 2048
#define DETS 100
#define IMG_WF 1333.0f
#define IMG_HF 800.0f
#define SCORE_T 0.05f
#define NMS_T 0.5f
#define MIN_SZ 0.01f
#define XCLIP 4.135166556742356f
#define FILL_HI 0xBF800000u   /* == desc_key(-1.0f) */
#define KEY_CAP 12288
#define SMEM_DYN (98304 + 16384)   /* keybuf/phaseB union + skeys */

__device__ u64 g_keys[(size_t)B_IMG * NCAND];
__device__ int g_count[B_IMG];            // zero-init; reset by k_tail each call
__device__ float2 g_smax[B_IMG * N_PROP];
__device__ float4 g_cand_box[B_IMG * K_TOP];

// accurate expf, immune to --use_fast_math (~2 ulp)
__device__ __forceinline__ float exp_acc(float x){
    float j = fmaf(x, 1.442695041f, 12582912.0f) - 12582912.0f;
    float f = fmaf(j, -0.693145752f, x);
    f = fmaf(j, -1.42860677e-6f, f);
    float r =          1.37805939e-3f;
    r = fmaf(r, f, 8.37312452e-3f);
    r = fmaf(r, f, 4.16695364e-2f);
    r = fmaf(r, f, 1.66664720e-1f);
    r = fmaf(r, f, 4.99999851e-1f);
    r = fmaf(r, f, 1.0f);
    r = fmaf(r, f, 1.0f);
    return ldexpf(r, (int)j);
}

// higher score -> smaller key
__device__ __forceinline__ u32 desc_key(float f){
    u32 u = __float_as_uint(f);
    u = (u & 0x80000000u) ? ~u : (u | 0x80000000u);
    return ~u;
}

__device__ __forceinline__ bool decode_box(float4 p, float4 r, float4& bx){
    float w  = p.z - p.x, h  = p.w - p.y;
    float cx = p.x + 0.5f*w, cy = p.y + 0.5f*h;
    float dx = __fdiv_rn(r.x, 10.0f), dy = __fdiv_rn(r.y, 10.0f);
    float dw = fminf(__fdiv_rn(r.z, 5.0f), XCLIP);
    float dh = fminf(__fdiv_rn(r.w, 5.0f), XCLIP);
    float pcx = dx*w + cx, pcy = dy*h + cy;
    float pw = exp_acc(dw)*w, ph = exp_acc(dh)*h;
    bx.x = fminf(fmaxf(pcx - 0.5f*pw, 0.0f), IMG_WF);
    bx.y = fminf(fmaxf(pcy - 0.5f*ph, 0.0f), IMG_HF);
    bx.z = fminf(fmaxf(pcx + 0.5f*pw, 0.0f), IMG_WF);
    bx.w = fminf(fmaxf(pcy + 0.5f*ph, 0.0f), IMG_HF);
    return ((bx.z - bx.x) >= MIN_SZ) && ((bx.w - bx.y) >= MIN_SZ);
}

__device__ __forceinline__ bool cand_full(int img, int idx,
        const float* __restrict__ logits, const float4* __restrict__ regs4,
        const float4* __restrict__ props4, float& score, float4& bx){
    int i_local = idx / NFG;
    int c = idx - i_local*NFG + 1;
    int i = img*N_PROP + i_local;
    float2 md = g_smax[i];
    float l = logits[(size_t)i*NCLS + c];
    score = __fdiv_rn(exp_acc(l - md.x), md.y);
    bool szok = decode_box(props4[i], regs4[(size_t)i*NCLS + c], bx);
    return (score > SCORE_T) && szok;
}

__global__ void __launch_bounds__(256) k_score(const float* __restrict__ logits,
                        const float4* __restrict__ regs4,
                        const float4* __restrict__ props4){
    __shared__ int s_cnt, s_base;
    int warp = threadIdx.x >> 5, lane = threadIdx.x & 31;
    int p = blockIdx.x*8 + warp;
    int img = p / N_PROP;
    int i_local = p - img*N_PROP;
    if (threadIdx.x == 0) s_cnt = 0;
    __syncthreads();
    const float* lrow = logits + (size_t)p*NCLS;
    float l0 = lrow[lane];
    float l1 = lrow[lane+32];
    float l2 = (lane < NCLS-64) ? lrow[lane+64] : -3.0e38f;
    float m = fmaxf(fmaxf(l0,l1), l2);
    #pragma unroll
    for (int o=16;o;o>>=1) m = fmaxf(m, __shfl_xor_sync(0xFFFFFFFFu, m, o));
    float e0 = exp_acc(l0-m), e1 = exp_acc(l1-m);
    float e2 = (lane < NCLS-64) ? exp_acc(l2-m) : 0.0f;
    float s = e0+e1+e2;
    #pragma unroll
    for (int o=16;o;o>>=1) s += __shfl_xor_sync(0xFFFFFFFFu, s, o);
    if (lane == 0) g_smax[p] = make_float2(m, s);
    float4 pr = props4[p];
    u64 karr[3]; int cnt = 0;
    #pragma unroll
    for (int slot=0; slot<3; slot++){
        int c = lane + slot*32;
        float e = (slot==0) ? e0 : ((slot==1) ? e1 : e2);
        if (c >= 1 && c < NCLS){
            float score = __fdiv_rn(e, s);
            if (score > SCORE_T){
                float4 bx;
                if (decode_box(pr, regs4[(size_t)p*NCLS + c], bx)){
                    u32 hi = desc_key(score);
                    karr[cnt++] = (((u64)hi) << 32)
                                | (u32)(i_local*NFG + (c-1));
                }
            }
        }
    }
    int pos = cnt ? atomicAdd(&s_cnt, cnt) : 0;
    __syncthreads();
    if (threadIdx.x == 0) s_base = atomicAdd(&g_count[img], s_cnt);
    __syncthreads();
    for (int k2=0; k2<cnt; k2++)
        g_keys[(size_t)img*NCAND + s_base + pos + k2] = karr[k2];
}

// register compare-exchange for bitonic stages j<=16 (in-warp)
__device__ __forceinline__ u64 cmpex(u64 v, int j, bool up){
    u64 p = __shfl_xor_sync(0xFFFFFFFFu, v, j);
    bool lower = ((threadIdx.x & j) == 0);
    u64 mn = v < p ? v : p;
    u64 mx = v < p ? p : v;
    return (lower == up) ? mn : mx;
}

__global__ void __launch_bounds__(1024) k_tail(const float* __restrict__ logits,
                        const float4* __restrict__ regs4,
                        const float4* __restrict__ props4,
                        float* __restrict__ out){
    extern __shared__ char dsm[];
    u64*            keybuf = (u64*)dsm;                      // phase A: 96KB
    float4*         s_ob   = (float4*)dsm;                   // phase B overlay
    float*          s_area = (float*)(dsm + 32768);
    unsigned short* s_ord  = (unsigned short*)(dsm + 40960);
    unsigned char*  s_lab  = (unsigned char*)(dsm + 45056);
    u64*            skeys  = (u64*)(dsm + 98304);            // 16KB, separate

    __shared__ u32 hist[256];
    __shared__ int s_hist[92], s_start[92];
    __shared__ u32 s_keep[64];
    __shared__ int s_wbase[64];
    __shared__ int wsum[32];
    __shared__ int s_digit, s_below, s_app, s_comp, s_tot;
    __shared__ u32 s_maxu;

    int img = blockIdx.x, tid = threadIdx.x;
    int warp = tid >> 5, lane = tid & 31;
    u64* buf = g_keys + (size_t)img*NCAND;
    int n0 = g_count[img];
    int n = n0;

    // ---- degenerate fill path (count < K_TOP): append invalids in index order
    if (n0 < K_TOP){
        if (tid == 0) s_app = 0;
        __syncthreads();
        for (int base = 0; base < NCAND; base += 1024){
            if (s_app >= K_TOP - n0) break;
            int idx = base + tid;
            bool flag = false;
            if (idx < NCAND){
                float sc; float4 bx;
                flag = !cand_full(img, idx, logits, regs4, props4, sc, bx);
            }
            u32 bal = __ballot_sync(0xFFFFFFFFu, flag);
            if (lane == 0) wsum[warp] = __popc(bal);
            __syncthreads();
            int off = 0, total = 0;
            #pragma unroll
            for (int wk = 0; wk < 32; wk++){ int v = wsum[wk]; if (wk < warp) off += v; total += v; }
            int rank = off + __popc(bal & ((1u<<lane)-1u));
            int need = K_TOP - n0 - s_app;
            if (flag && rank < need)
                buf[n0 + s_app + rank] = (((u64)FILL_HI)<<32) | (u32)idx;
            __syncthreads();
            if (tid == 0) s_app += (total < need ? total : need);
            __syncthreads();
        }
        n = K_TOP;
        __syncthreads();
    }

    // ---- stage keys in smem when they fit
    bool insm = (n <= KEY_CAP);
    if (insm){
        for (int j = tid; j < n; j += 1024) keybuf[j] = buf[j];
        __syncthreads();
    }
    const u64* kb = insm ? (const u64*)keybuf : (const u64*)buf;

    // ---- exact K_TOP-th key via MSB radix select (keys unique)
    u64 T = ~0ull;
    if (n > K_TOP){
        u64 prefix = 0, himask = 0;
        u32 kk = K_TOP;
        for (int pass = 0; pass < 8; pass++){
            int shift = 56 - 8*pass;
            if (tid < 256) hist[tid] = 0u;
            __syncthreads();
            for (int jj = tid; jj < n; jj += 1024){
                u64 key = kb[jj];
                if ((key & himask) == prefix)
                    atomicAdd(&hist[(u32)(key>>shift)&255u], 1u);
            }
            __syncthreads();
            if (warp == 0){
                u32 loc[8], sum = 0;
                #pragma unroll
                for (int r = 0; r < 8; r++){ loc[r] = hist[lane*8+r]; sum += loc[r]; }
                u32 inc = sum;
                #pragma unroll
                for (int o = 1; o < 32; o <<= 1){
                    u32 v = __shfl_up_sync(0xFFFFFFFFu, inc, o);
                    if (lane >= o) inc += v;
                }
                u32 excl = inc - sum;
                if (kk > excl && kk <= inc){
                    u32 cum = excl;
                    #pragma unroll
                    for (int r = 0; r < 8; r++){
                        if (cum + loc[r] >= kk){ s_digit = lane*8+r; s_below = (int)cum; break; }
                        cum += loc[r];
                    }
                }
            }
            __syncthreads();
            prefix |= ((u64)(u32)s_digit) << shift;
            kk -= (u32)s_below;
            himask = (~0ull) << shift;
            __syncthreads();
        }
        T = prefix;
    }

    // ---- compact exactly K_TOP selected keys into skeys
    if (tid == 0) s_comp = 0;
    __syncthreads();
    for (int jj = tid; jj < n; jj += 1024){
        u64 key = kb[jj];
        if (key <= T){
            int pp = atomicAdd(&s_comp, 1);
            if (pp < K_TOP) skeys[pp] = key;
        }
    }
    __syncthreads();

    // ---- bitonic sort 2048 keys, 1024 threads, j<=16 stages in registers
    {
        u64 a = skeys[tid], b = skeys[tid + 1024];
        #pragma unroll
        for (int k = 2; k <= 32; k <<= 1){
            bool upa = ((tid & k) == 0);
            bool upb = (((tid + 1024) & k) == 0);
            #pragma unroll
            for (int j = k >> 1; j >= 1; j >>= 1){
                a = cmpex(a, j, upa);
                b = cmpex(b, j, upb);
            }
        }
        skeys[tid] = a; skeys[tid + 1024] = b;
        __syncthreads();
        for (int k = 64; k <= K_TOP; k <<= 1){
            for (int j = k >> 1; j >= 32; j >>= 1){
                int ii = ((tid & ~(j-1)) << 1) | (tid & (j-1));
                int pp = ii | j;
                bool up = ((ii & k) == 0);
                u64 x = skeys[ii], y = skeys[pp];
                if ((x > y) == up){ skeys[ii] = y; skeys[pp] = x; }
                __syncthreads();
            }
            a = skeys[tid]; b = skeys[tid + 1024];
            bool upa = ((tid & k) == 0);
            bool upb = (((tid + 1024) & k) == 0);
            #pragma unroll
            for (int j = 16; j >= 1; j >>= 1){
                a = cmpex(a, j, upa);
                b = cmpex(b, j, upb);
            }
            skeys[tid] = a; skeys[tid + 1024] = b;
            __syncthreads();
        }
    }

    // ---- decode candidates (score comes from key bits; no logits reload)
    if (tid < 64) s_keep[tid] = 0u;
    if (tid < 92) s_hist[tid] = 0;
    if (tid == 0) s_maxu = 0u;
    __syncthreads();
    u32 lmax = 0u;
    for (int s = tid; s < K_TOP; s += 1024){
        u64 key = skeys[s];
        u32 hi = (u32)(key >> 32);
        int idx = (int)(key & 0xFFFFFFFFull);
        int il = idx / NFG;
        int c = idx - il*NFG + 1;
        int i = img*N_PROP + il;
        float4 bx;
        decode_box(props4[i], regs4[(size_t)i*NCLS + c], bx);
        g_cand_box[img*K_TOP + s] = bx;
        s_lab[s] = (unsigned char)c;
        atomicAdd(&s_hist[c], 1);
        if (hi != FILL_HI) atomicOr(&s_keep[s>>5], 1u<<(s&31));
        float mx = fmaxf(fmaxf(bx.x, bx.y), fmaxf(bx.z, bx.w));
        u32 mxu = __float_as_uint(mx);
        lmax = lmax > mxu ? lmax : mxu;
    }
    #pragma unroll
    for (int o = 16; o; o >>= 1){
        u32 v = __shfl_xor_sync(0xFFFFFFFFu, lmax, o);
        lmax = lmax > v ? lmax : v;
    }
    if (lane == 0) atomicMax(&s_maxu, lmax);
    __syncthreads();
    float mul = __uint_as_float(s_maxu) + 1.0f;
    for (int s = tid; s < K_TOP; s += 1024){
        float4 b = g_cand_box[img*K_TOP + s];
        float off = (float)s_lab[s] * mul;
        float4 ob = make_float4(b.x+off, b.y+off, b.z+off, b.w+off);
        s_ob[s] = ob;
        s_area[s] = (ob.z - ob.x) * (ob.w - ob.y);
    }
    if (tid == 0){ int acc = 0; for (int l = 0; l < 92; l++){ s_start[l] = acc; acc += s_hist[l]; } }
    __syncthreads();

    // ---- counting sort into per-label order (score order preserved)
    #pragma unroll
    for (int k3 = 0; k3 < 3; k3++){
        int lab = 1 + warp + k3*32;
        if (lab <= NFG){
            int cur = 0, st = s_start[lab];
            for (int base = 0; base < K_TOP; base += 32){
                int t2 = base + lane;
                bool mm = (s_lab[t2] == (unsigned char)lab);
                u32 bal = __ballot_sync(0xFFFFFFFFu, mm);
                if (mm) s_ord[st + cur + __popc(bal & ((1u<<lane)-1u))] = (unsigned short)t2;
                cur += __popc(bal);
            }
        }
    }
    __syncthreads();

    // ---- per-label greedy NMS, one warp per label
    #pragma unroll
    for (int k3 = 0; k3 < 3; k3++){
        int lab = 1 + warp + k3*32;
        if (lab > NFG) continue;
        int st = s_start[lab], g = s_hist[lab];
        for (int i = 0; i < g; i++){
            int ci = s_ord[st+i];
            u32 kw = s_keep[ci>>5];
            if (!((kw >> (ci&31)) & 1u)){ __syncwarp(); continue; }
            float4 a2 = s_ob[ci]; float aa = s_area[ci];
            for (int j = i+1+lane; j < g; j += 32){
                int cj = s_ord[st+j];
                float4 bb = s_ob[cj];
                float ltx = fmaxf(a2.x, bb.x), lty = fmaxf(a2.y, bb.y);
                float rbx = fminf(a2.z, bb.z), rby = fminf(a2.w, bb.w);
                float wx = fmaxf(rbx-ltx, 0.0f), wy = fmaxf(rby-lty, 0.0f);
                float inter = wx*wy;
                float iou = __fdiv_rn(inter, aa + s_area[cj] - inter);
                if (iou > NMS_T) atomicAnd(&s_keep[cj>>5], ~(1u<<(cj&31)));
            }
            __syncwarp();
        }
    }
    __syncthreads();

    // ---- prefix scan over keep bits (warp 0)
    if (warp == 0){
        u32 w0 = s_keep[lane];
        int c0 = __popc(w0), sc0 = c0;
        #pragma unroll
        for (int o=1;o<32;o<<=1){ int v=__shfl_up_sync(0xFFFFFFFFu,sc0,o); if(lane>=o) sc0+=v; }
        s_wbase[lane] = sc0 - c0;
        int tot0 = __shfl_sync(0xFFFFFFFFu, sc0, 31);
        u32 w1 = s_keep[32+lane];
        int c1 = __popc(w1), sc1 = c1;
        #pragma unroll
        for (int o=1;o<32;o<<=1){ int v=__shfl_up_sync(0xFFFFFFFFu,sc1,o); if(lane>=o) sc1+=v; }
        s_wbase[32+lane] = tot0 + sc1 - c1;
        if (lane == 31) s_tot = tot0 + sc1;
    }
    __syncthreads();
    int K = s_tot;

    // ---- emit top-100 (kept in order, then non-kept with score -1)
    for (int t2 = tid; t2 < K_TOP; t2 += 1024){
        u32 w = s_keep[t2>>5];
        int kbefore = s_wbase[t2>>5] + __popc(w & ((1u<<(t2&31))-1u));
        bool kept = (w >> (t2&31)) & 1u;
        int slot = -1; float osc = 0.0f;
        if (kept){
            if (kbefore < DETS){
                slot = kbefore;
                u32 hi = (u32)(skeys[t2] >> 32);
                osc = __uint_as_float(~hi & 0x7FFFFFFFu);
            }
        } else if (K < DETS){
            int s2 = K + (t2 - kbefore);
            if (s2 < DETS){ slot = s2; osc = -1.0f; }
        }
        if (slot >= 0){
            ((float4*)out)[img*DETS + slot] = g_cand_box[img*K_TOP + t2];
            out[B_IMG*DETS*4 + img*DETS + slot] = osc;
            out[B_IMG*DETS*5 + img*DETS + slot] = (float)s_lab[t2];
        }
    }

    // reset for next invocation (deterministic: every call leaves zeroed state)
    __syncthreads();
    if (tid == 0) g_count[img] = 0;
}

extern "C" void kernel_launch(void* const* d_in, const int* in_sizes, int n_in,
                              void* d_out, int out_size) {
    const float*  logits = (const float*)d_in[0];
    const float4* regs4  = (const float4*)d_in[1];
    const float4* props4 = (const float4*)d_in[2];
    float* out = (float*)d_out;
    cudaFuncSetAttribute(k_tail, cudaFuncAttributeMaxDynamicSharedMemorySize, SMEM_DYN);
    k_score<<<(B_IMG*N_PROP)/8, 256>>>(logits, regs4, props4);
    k_tail<<<B_IMG, 1024, SMEM_DYN>>>(logits, regs4, props4, out);
}